// round 9
// baseline (speedup 1.0000x reference)
#include <cuda_runtime.h>
#include <cuda_fp16.h>
#include <cstdint>

// QuadraticConv2D implicit GEMM, fp16 mma.sync, f16 accumulator chains
// promoted to fp32 once per feature. M=65536, K=54*64 (+exact bias), N=64.
// CTA: 256 thr, 256 m rows (4 image rows), warp tile m32n64, grid 256 (1 wave).
// Channel-interleaved smem layout: (k-lo pair, k-hi pair) adjacent -> every
// A/B fragment fetch is one ld.shared.v2.u32. 160B slot stride -> lane pattern
// 8r+2t4 mod 32 -> conflict-free 64-bit LDS.

#define XS_SLOT   160                  // bytes per (row,w) slot: 128B data+32B pad
#define XS_ROWB   (66 * XS_SLOT)       // 10560 B per image row (w = -1..64)
#define XS_BYTES  (6 * XS_ROWB)        // 63360
#define WS_BUF    10240                // 64 o-rows x 160B
#define NBUF      4                    // MUST exceed prefetch distance 3
#define SMEM_BYTES (XS_BYTES + NBUF * WS_BUF)   // 104320

__device__ __align__(16) __half Wg[54 * 5120];   // [l][o][interleaved c]
__device__ float bvecg[64];                       // exact bias (fp32)

__constant__ unsigned char F_I[54] = {
    0,0,0,0,0,0,0,0,0,0, 1,1,1,1,1,1,1,1,1, 2,2,2,2,2,2,2,2,
    3,3,3,3,3,3,3, 4,4,4,4,4,4, 5,5,5,5,5, 6,6,6,6, 7,7,7, 8,8};
__constant__ unsigned char F_J[54] = {
    0,1,2,3,4,5,6,7,8,255, 1,2,3,4,5,6,7,8,255, 2,3,4,5,6,7,8,255,
    3,4,5,6,7,8,255, 4,5,6,7,8,255, 5,6,7,8,255, 6,7,8,255, 7,8,255, 8,255};
__constant__ unsigned char F_L[54] = {
    0,1,2,3,4,5,6,7,8,45, 9,10,11,12,13,14,15,16,46, 17,18,19,20,21,22,23,47,
    24,25,26,27,28,29,48, 30,31,32,33,34,49, 35,36,37,38,50,
    39,40,41,51, 42,43,52, 44,53};

// interleaved byte offset of channel-pair (c even) within a 160B slot:
// pair(16q+2t4) at q*32+t4*8, pair(16q+8+2t4) at q*32+t4*8+4.
__device__ __host__ static inline int coff(int c) {
    return ((c >> 4) << 5) + (((c & 7) >> 1) << 3) + (((c >> 3) & 1) << 2)
         + ((c & 1) << 1);
}

static __device__ __forceinline__ void mma_h_zero(uint32_t* d,
    uint32_t a0, uint32_t a1, uint32_t a2, uint32_t a3,
    uint32_t b0, uint32_t b1) {
    asm volatile(
        "mma.sync.aligned.m16n8k16.row.col.f16.f16.f16.f16 "
        "{%0,%1}, {%2,%3,%4,%5}, {%6,%7}, {%8,%8};"
        : "=r"(d[0]), "=r"(d[1])
        : "r"(a0), "r"(a1), "r"(a2), "r"(a3), "r"(b0), "r"(b1), "r"(0u));
}
static __device__ __forceinline__ void mma_h_acc(uint32_t* d,
    uint32_t a0, uint32_t a1, uint32_t a2, uint32_t a3,
    uint32_t b0, uint32_t b1) {
    asm volatile(
        "mma.sync.aligned.m16n8k16.row.col.f16.f16.f16.f16 "
        "{%0,%1}, {%2,%3,%4,%5}, {%6,%7}, {%0,%1};"
        : "+r"(d[0]), "+r"(d[1])
        : "r"(a0), "r"(a1), "r"(a2), "r"(a3), "r"(b0), "r"(b1));
}
static __device__ __forceinline__ void lds64(uint32_t& a, uint32_t& b,
                                             uint32_t addr) {
    asm volatile("ld.shared.v2.u32 {%0,%1}, [%2];"
                 : "=r"(a), "=r"(b) : "r"(addr));
}

__global__ void prep_W(const float* __restrict__ wk) {
    const int l = blockIdx.x;
    if (l < 54) {
        for (int idx = threadIdx.x; idx < 4096; idx += 256) {
            const int o = idx >> 6, c = idx & 63;
            Wg[l * 5120 + o * 80 + (coff(c) >> 1)] =
                __float2half_rn(wk[l * 4096 + c * 64 + o]);
        }
    } else if (threadIdx.x < 64) {
        float s = 0.f;
        for (int c = 0; c < 64; ++c) s += wk[54 * 4096 + c * 64 + threadIdx.x];
        bvecg[threadIdx.x] = s;
    }
}

static __device__ __forceinline__ void issue_w_cp(uint32_t dst, int l, int t) {
    const char* src = (const char*)Wg + (size_t)F_L[l] * WS_BUF;
    asm volatile("cp.async.ca.shared.global [%0], [%1], 16;"
                 :: "r"(dst + t * 16), "l"(src + t * 16) : "memory");
    asm volatile("cp.async.ca.shared.global [%0], [%1], 16;"
                 :: "r"(dst + (t + 256) * 16), "l"(src + (t + 256) * 16) : "memory");
    if (t < 128)
        asm volatile("cp.async.ca.shared.global [%0], [%1], 16;"
                     :: "r"(dst + (t + 512) * 16), "l"(src + (t + 512) * 16) : "memory");
    asm volatile("cp.async.commit_group;" ::: "memory");
}

__global__ __launch_bounds__(256, 2)
void qconv_mma(const float* __restrict__ x, float* __restrict__ out) {
    extern __shared__ unsigned char xsm[];
    const uint32_t sb  = (uint32_t)__cvta_generic_to_shared(xsm);
    const uint32_t wsB = sb + XS_BYTES;

    const int t    = threadIdx.x;
    const int warp = t >> 5, lane = t & 31;
    const int r    = lane >> 2, t4 = lane & 3;
    const int irow  = warp >> 1;          // image row within CTA (0..3)
    const int wbase = (warp & 1) * 32;    // w offset within image row
    const int bb = blockIdx.x >> 4;
    const int r0 = (blockIdx.x & 15) * 4;

    // ---- stage 6 x-rows as interleaved fp16 (160B slots, zero halo) ----
    #pragma unroll
    for (int rr = 0; rr < 6; ++rr) {
        const int hh = r0 + rr - 1;
        const bool ok = (hh >= 0 && hh < 64);
        const float4* src = (const float4*)(x + (size_t)(bb * 64 + (ok ? hh : 0)) * 4096);
        #pragma unroll
        for (int k = 0; k < 4; ++k) {
            const int idx = t + k * 256;          // float4 idx 0..1023
            const int ww = idx >> 4, c4 = idx & 15;
            float4 v = ok ? src[idx] : make_float4(0.f, 0.f, 0.f, 0.f);
            const __half2 h0 = __floats2half2_rn(v.x, v.y);
            const __half2 h1 = __floats2half2_rn(v.z, v.w);
            unsigned char* p = xsm + rr * XS_ROWB + (ww + 1) * XS_SLOT + coff(c4 * 4);
            *(uint32_t*)p       = *(const uint32_t*)&h0;
            *(uint32_t*)(p + 8) = *(const uint32_t*)&h1;
        }
    }
    if (t < 192) {   // halo slots w=-1 and w=64: zero 128B each of 6 rows
        const int rr = t >> 5, side = (t >> 4) & 1, c8 = t & 15;
        *(uint2*)(xsm + rr * XS_ROWB + (side ? 65 : 0) * XS_SLOT + c8 * 8) =
            make_uint2(0u, 0u);
    }

    issue_w_cp(wsB + 0 * WS_BUF, 0, t);
    issue_w_cp(wsB + 1 * WS_BUF, 1, t);
    issue_w_cp(wsB + 2 * WS_BUF, 2, t);

    float acc[2][8][4];                  // [m16 blk][n8 blk][4]
    #pragma unroll
    for (int a = 0; a < 2; ++a)
        #pragma unroll
        for (int b = 0; b < 8; ++b)
            #pragma unroll
            for (int cc = 0; cc < 4; ++cc) acc[a][b][cc] = 0.f;

    for (int f = 0; f < 54; ++f) {
        if (f < 52)       asm volatile("cp.async.wait_group 2;" ::: "memory");
        else if (f == 52) asm volatile("cp.async.wait_group 1;" ::: "memory");
        else              asm volatile("cp.async.wait_group 0;" ::: "memory");
        __syncthreads();

        if (f + 3 < 54) issue_w_cp(wsB + ((f + 3) & 3) * WS_BUF, f + 3, t);

        const int ii = F_I[f], jj = F_J[f];
        const int di = ii / 3, dj = ii % 3;
        const bool quad = (jj != 255);
        const int dr = quad ? jj / 3 : 0, dc = quad ? jj % 3 : 0;

        // ---- build per-feature A fragments ha[q][mi][2] ----
        uint32_t ib[4], jb[4];
        #pragma unroll
        for (int mi = 0; mi < 4; ++mi) {
            const int wp = wbase + mi * 8 + r;
            ib[mi] = sb + (irow + di) * XS_ROWB + (wp + dj) * XS_SLOT + t4 * 8;
            jb[mi] = sb + (irow + dr) * XS_ROWB + (wp + dc) * XS_SLOT + t4 * 8;
        }
        uint32_t ha[4][4][2];
        #pragma unroll
        for (int q = 0; q < 4; ++q) {
            #pragma unroll
            for (int mi = 0; mi < 4; ++mi) {
                uint32_t v0, v1;
                lds64(v0, v1, ib[mi] + q * 32);
                if (quad) {
                    uint32_t w0, w1;
                    lds64(w0, w1, jb[mi] + q * 32);
                    const __half2 p0 = __hmul2(*(const __half2*)&v0,
                                               *(const __half2*)&w0);
                    const __half2 p1 = __hmul2(*(const __half2*)&v1,
                                               *(const __half2*)&w1);
                    v0 = *(const uint32_t*)&p0;
                    v1 = *(const uint32_t*)&p1;
                }
                ha[q][mi][0] = v0;
                ha[q][mi][1] = v1;
            }
        }

        // ---- MMA in four n16 slices, f16 chains, promote per slice ----
        const uint32_t wb = wsB + (f & 3) * WS_BUF;
        #pragma unroll
        for (int nh = 0; nh < 4; ++nh) {
            uint32_t dfr[2][2][2];
            #pragma unroll
            for (int q = 0; q < 4; ++q) {
                #pragma unroll
                for (int n2 = 0; n2 < 2; ++n2) {
                    uint32_t b0, b1;
                    lds64(b0, b1,
                          wb + ((nh * 2 + n2) * 8 + r) * XS_SLOT + q * 32 + t4 * 8);
                    if (q == 0) {
                        mma_h_zero(dfr[0][n2], ha[0][0][0], ha[0][1][0],
                                   ha[0][0][1], ha[0][1][1], b0, b1);
                        mma_h_zero(dfr[1][n2], ha[0][2][0], ha[0][3][0],
                                   ha[0][2][1], ha[0][3][1], b0, b1);
                    } else {
                        mma_h_acc(dfr[0][n2], ha[q][0][0], ha[q][1][0],
                                  ha[q][0][1], ha[q][1][1], b0, b1);
                        mma_h_acc(dfr[1][n2], ha[q][2][0], ha[q][3][0],
                                  ha[q][2][1], ha[q][3][1], b0, b1);
                    }
                }
            }
            #pragma unroll
            for (int mb = 0; mb < 2; ++mb)
                #pragma unroll
                for (int n2 = 0; n2 < 2; ++n2) {
                    const float2 lo =
                        __half22float2(*(const __half2*)&dfr[mb][n2][0]);
                    const float2 hi =
                        __half22float2(*(const __half2*)&dfr[mb][n2][1]);
                    float* a = acc[mb][nh * 2 + n2];
                    a[0] += lo.x; a[1] += lo.y; a[2] += hi.x; a[3] += hi.y;
                }
        }
    }

    // ---- epilogue: exact bias add + float2 stores ----
    const int mrow0 = blockIdx.x * 256 + warp * 32 + r;
    #pragma unroll
    for (int mb = 0; mb < 2; ++mb) {
        #pragma unroll
        for (int nt = 0; nt < 8; ++nt) {
            const int n = nt * 8 + t4 * 2;
            const float bvx = bvecg[n], bvy = bvecg[n + 1];
            float* o0 = out + (size_t)(mrow0 + mb * 16) * 64 + n;
            *(float2*)o0 = make_float2(acc[mb][nt][0] + bvx, acc[mb][nt][1] + bvy);
            *(float2*)(o0 + 8 * 64) =
                make_float2(acc[mb][nt][2] + bvx, acc[mb][nt][3] + bvy);
        }
    }
}

extern "C" void kernel_launch(void* const* d_in, const int* in_sizes, int n_in,
                              void* d_out, int out_size) {
    const float* x  = (const float*)d_in[0];
    const float* wk = (const float*)d_in[1];   // [55,64,64] (l,c,o) contiguous
    float* out = (float*)d_out;

    prep_W<<<55, 256>>>(wk);
    cudaFuncSetAttribute(qconv_mma,
                         cudaFuncAttributeMaxDynamicSharedMemorySize, SMEM_BYTES);
    qconv_mma<<<256, 256, SMEM_BYTES>>>(x, out);
}

// round 10
// speedup vs baseline: 1.5315x; 1.5315x over previous
#include <cuda_runtime.h>
#include <cuda_fp16.h>
#include <cstdint>

// QuadraticConv2D implicit GEMM on fp16 mma.sync (f32 accumulate).
// out[m,o] = sum_{l,c} F_l[m,c] * W[l,c,o];  M=65536, K=54*64 (+exact bias), N=64.
// CTA: 256 thr, 256 m rows (4 image rows), warp tile m32n64, grid 256.
// x staged fp16 in smem (57KB, conflict-free stride-72).
// W pre-packed in FRAGMENT order; B fragments come via coalesced LDG.128
// (L1/L2-cached) -> no W smem, no cp.async, NO barriers in the main loop.

#define XS_STRIDE 72                    // halfs per w position (conflict-free)
#define XS_ROW    (66 * XS_STRIDE)      // 4752 halfs per image row
#define XS_HALFS  (6 * XS_ROW)          // 28512
#define SMEM_BYTES (XS_HALFS * 2)       // 57024 B

// Fragment-packed weights: Wf[l][q][g2][lane] -> uint4 =
//   { b0(nt=2g2), b1(2g2), b0(2g2+1), b1(2g2+1) } for that lane.
// b0 = halfs (k=16q+2t4, 16q+2t4+1 ; n = nt*8+r), b1 = same with k+8.
__device__ __align__(16) uint4 Wfg[54 * 16 * 32];
__device__ float bvecg[64];             // exact bias contribution (fp32)

__constant__ unsigned char F_I[54] = {
    0,0,0,0,0,0,0,0,0,0, 1,1,1,1,1,1,1,1,1, 2,2,2,2,2,2,2,2,
    3,3,3,3,3,3,3, 4,4,4,4,4,4, 5,5,5,5,5, 6,6,6,6, 7,7,7, 8,8};
__constant__ unsigned char F_J[54] = {
    0,1,2,3,4,5,6,7,8,255, 1,2,3,4,5,6,7,8,255, 2,3,4,5,6,7,8,255,
    3,4,5,6,7,8,255, 4,5,6,7,8,255, 5,6,7,8,255, 6,7,8,255, 7,8,255, 8,255};
__constant__ unsigned char F_L[54] = {
    0,1,2,3,4,5,6,7,8,45, 9,10,11,12,13,14,15,16,46, 17,18,19,20,21,22,23,47,
    24,25,26,27,28,29,48, 30,31,32,33,34,49, 35,36,37,38,50,
    39,40,41,51, 42,43,52, 44,53};

static __device__ __forceinline__ void mma16816(float* d,
    uint32_t a0, uint32_t a1, uint32_t a2, uint32_t a3,
    uint32_t b0, uint32_t b1) {
    asm volatile(
        "mma.sync.aligned.m16n8k16.row.col.f32.f16.f16.f32 "
        "{%0,%1,%2,%3}, {%4,%5,%6,%7}, {%8,%9}, {%0,%1,%2,%3};"
        : "+f"(d[0]), "+f"(d[1]), "+f"(d[2]), "+f"(d[3])
        : "r"(a0), "r"(a1), "r"(a2), "r"(a3), "r"(b0), "r"(b1));
}
static __device__ __forceinline__ uint32_t lds32(uint32_t addr) {
    uint32_t v;
    asm volatile("ld.shared.b32 %0, [%1];" : "=r"(v) : "r"(addr));
    return v;
}
static __device__ __forceinline__ uint32_t packh2(float a, float b) {
    const __half2 h = __floats2half2_rn(a, b);
    return *(const uint32_t*)&h;
}

// ---- prep: fragment-pack W into Wfg; exact fp32 bias column sums ----
__global__ void prep_W(const float* __restrict__ wk) {
    const int l = blockIdx.x;
    if (l < 54) {
        const int tid = threadIdx.x;          // 512 threads = 16 frag-groups x 32
        const int q    = tid >> 7;
        const int g2   = (tid >> 5) & 3;
        const int lane = tid & 31;
        const int r = lane >> 2, t4 = lane & 3;
        const int n0 = (2 * g2) * 8 + r;
        const int n1 = (2 * g2 + 1) * 8 + r;
        const int k0 = 16 * q + 2 * t4;
        const float* w = wk + l * 4096;
        uint4 v;
        v.x = packh2(w[(k0    ) * 64 + n0], w[(k0 + 1) * 64 + n0]);
        v.y = packh2(w[(k0 + 8) * 64 + n0], w[(k0 + 9) * 64 + n0]);
        v.z = packh2(w[(k0    ) * 64 + n1], w[(k0 + 1) * 64 + n1]);
        v.w = packh2(w[(k0 + 8) * 64 + n1], w[(k0 + 9) * 64 + n1]);
        Wfg[(l * 16 + q * 4 + g2) * 32 + lane] = v;
    } else if (threadIdx.x < 64) {
        float s = 0.f;
        for (int c = 0; c < 64; ++c) s += wk[54 * 4096 + c * 64 + threadIdx.x];
        bvecg[threadIdx.x] = s;
    }
}

// --------------------------------- main -------------------------------------
__global__ __launch_bounds__(256, 2)
void qconv_mma(const float* __restrict__ x, float* __restrict__ out) {
    extern __shared__ __half xsm[];
    __half* xs = xsm;
    const uint32_t sb = (uint32_t)__cvta_generic_to_shared(xsm);

    const int t    = threadIdx.x;
    const int warp = t >> 5, lane = t & 31;
    const int r    = lane >> 2, t4 = lane & 3;
    const int irow  = warp >> 1;          // image row within CTA (0..3)
    const int wbase = (warp & 1) * 32;    // w offset within image row
    const int bb = blockIdx.x >> 4;
    const int r0 = (blockIdx.x & 15) * 4;

    // ---- stage 6 x-rows as fp16 (stride-72, zero halo) ----
    #pragma unroll
    for (int rr = 0; rr < 6; ++rr) {
        const int hh = r0 + rr - 1;
        const bool ok = (hh >= 0 && hh < 64);
        const float4* src =
            (const float4*)(x + (size_t)(bb * 64 + (ok ? hh : 0)) * 4096);
        #pragma unroll
        for (int k = 0; k < 4; ++k) {
            const int idx = t + k * 256;          // float4 idx 0..1023
            const int ww = idx >> 4, c4 = idx & 15;
            const float4 v = ok ? src[idx] : make_float4(0.f, 0.f, 0.f, 0.f);
            uint2 pk;
            pk.x = packh2(v.x, v.y);
            pk.y = packh2(v.z, v.w);
            *(uint2*)(xs + rr * XS_ROW + (ww + 1) * XS_STRIDE + c4 * 4) = pk;
        }
    }
    if (t < 192) {
        const int rr = t >> 5, side = (t >> 4) & 1, c4 = t & 15;
        *(uint2*)(xs + rr * XS_ROW + (side ? 65 : 0) * XS_STRIDE + c4 * 4) =
            make_uint2(0u, 0u);
    }
    __syncthreads();          // the ONLY barrier

    float acc[2][8][4];
    #pragma unroll
    for (int a = 0; a < 2; ++a)
        #pragma unroll
        for (int b = 0; b < 8; ++b)
            #pragma unroll
            for (int cc = 0; cc < 4; ++cc) acc[a][b][cc] = 0.f;

    for (int f = 0; f < 54; ++f) {
        const int ii = F_I[f], jj = F_J[f];
        const int di = ii / 3, dj = ii % 3;
        const bool quad = (jj != 255);
        const int dr = quad ? jj / 3 : 0, dc = quad ? jj % 3 : 0;

        uint32_t ib[4], jb[4];
        #pragma unroll
        for (int mi = 0; mi < 4; ++mi) {
            const int wp = wbase + mi * 8 + r;
            ib[mi] = sb + ((irow + di) * XS_ROW + (wp + dj) * XS_STRIDE) * 2
                   + t4 * 4;
            jb[mi] = sb + ((irow + dr) * XS_ROW + (wp + dc) * XS_STRIDE) * 2
                   + t4 * 4;
        }

        const uint4* wf = Wfg + (size_t)(F_L[f] * 16) * 32 + lane;

        #pragma unroll
        for (int q = 0; q < 4; ++q) {
            // B fragments: 4 coalesced LDG.128 (L1/L2-resident)
            uint4 bv[4];
            #pragma unroll
            for (int g2 = 0; g2 < 4; ++g2)
                bv[g2] = __ldg(wf + (q * 4 + g2) * 32);

            // A fragments: tap loads (+ optional HMUL2 for quadratic terms)
            uint32_t ha[4][2];
            #pragma unroll
            for (int mi = 0; mi < 4; ++mi) {
                uint32_t v0 = lds32(ib[mi] + q * 32);
                uint32_t v1 = lds32(ib[mi] + q * 32 + 16);
                if (quad) {
                    const uint32_t w0 = lds32(jb[mi] + q * 32);
                    const uint32_t w1 = lds32(jb[mi] + q * 32 + 16);
                    const __half2 p0 = __hmul2(*(const __half2*)&v0,
                                               *(const __half2*)&w0);
                    const __half2 p1 = __hmul2(*(const __half2*)&v1,
                                               *(const __half2*)&w1);
                    v0 = *(const uint32_t*)&p0;
                    v1 = *(const uint32_t*)&p1;
                }
                ha[mi][0] = v0;
                ha[mi][1] = v1;
            }

            #pragma unroll
            for (int g2 = 0; g2 < 4; ++g2) {
                mma16816(acc[0][2 * g2],     ha[0][0], ha[1][0], ha[0][1],
                         ha[1][1], bv[g2].x, bv[g2].y);
                mma16816(acc[0][2 * g2 + 1], ha[0][0], ha[1][0], ha[0][1],
                         ha[1][1], bv[g2].z, bv[g2].w);
                mma16816(acc[1][2 * g2],     ha[2][0], ha[3][0], ha[2][1],
                         ha[3][1], bv[g2].x, bv[g2].y);
                mma16816(acc[1][2 * g2 + 1], ha[2][0], ha[3][0], ha[2][1],
                         ha[3][1], bv[g2].z, bv[g2].w);
            }
        }
    }

    // ---- epilogue: exact bias add + float2 stores ----
    const int mrow0 = blockIdx.x * 256 + warp * 32 + r;
    #pragma unroll
    for (int mb = 0; mb < 2; ++mb) {
        #pragma unroll
        for (int nt = 0; nt < 8; ++nt) {
            const int n = nt * 8 + t4 * 2;
            const float bvx = bvecg[n], bvy = bvecg[n + 1];
            float* o0 = out + (size_t)(mrow0 + mb * 16) * 64 + n;
            *(float2*)o0 = make_float2(acc[mb][nt][0] + bvx, acc[mb][nt][1] + bvy);
            *(float2*)(o0 + 8 * 64) =
                make_float2(acc[mb][nt][2] + bvx, acc[mb][nt][3] + bvy);
        }
    }
}

extern "C" void kernel_launch(void* const* d_in, const int* in_sizes, int n_in,
                              void* d_out, int out_size) {
    const float* x  = (const float*)d_in[0];
    const float* wk = (const float*)d_in[1];   // [55,64,64] (l,c,o) contiguous
    float* out = (float*)d_out;

    prep_W<<<55, 512>>>(wk);
    cudaFuncSetAttribute(qconv_mma,
                         cudaFuncAttributeMaxDynamicSharedMemorySize, SMEM_BYTES);
    qconv_mma<<<256, 256, SMEM_BYTES>>>(x, out);
}